// round 4
// baseline (speedup 1.0000x reference)
#include <cuda_runtime.h>
#include <cstdint>

// Problem constants
#define B_   32
#define NQ_  16384
#define NK_  31
#define DM_  64
#define H_   4
#define DH_  16

#define NTHREADS_A 128
#define ROWS_PER_BLOCK_A (NTHREADS_A * 2)   // 256 (2 rows per thread)

#define NTHREADS_B 256

// log2(e) / sqrt(d_head)
#define LOG2E_OVER_SCALE 0.36067376022224085f

typedef unsigned long long ull;

// Out-projection weights (ORIGINAL [j][i] layout) + bias in constant memory.
__constant__ float cW[DM_ * DM_];
__constant__ float cb[DM_];

// ---------------- f32x2 helpers ----------------

__device__ __forceinline__ ull pack2(float lo, float hi) {
    ull r;
    asm("mov.b64 %0, {%1, %2};" : "=l"(r) : "f"(lo), "f"(hi));
    return r;
}

__device__ __forceinline__ void unpack2(ull v, float& lo, float& hi) {
    asm("mov.b64 {%0, %1}, %2;" : "=f"(lo), "=f"(hi) : "l"(v));
}

__device__ __forceinline__ ull fma2(ull a, ull b, ull c) {
    ull d;
    asm("fma.rn.f32x2 %0, %1, %2, %3;" : "=l"(d) : "l"(a), "l"(b), "l"(c));
    return d;
}

__device__ __forceinline__ ull mul2(ull a, ull b) {
    ull d;
    asm("mul.rn.f32x2 %0, %1, %2;" : "=l"(d) : "l"(a), "l"(b));
    return d;
}

__device__ __forceinline__ void lds_v2u64(uint32_t addr, ull& a, ull& b) {
    asm("ld.shared.v2.u64 {%0, %1}, [%2];" : "=l"(a), "=l"(b) : "r"(addr));
}

__device__ __forceinline__ void ldc_v2u64(ull addr, ull& a, ull& b) {
    asm("ld.const.v2.u64 {%0, %1}, [%2];" : "=l"(a), "=l"(b) : "l"(addr));
}

__device__ __forceinline__ float ldc_f32(ull addr) {
    float v;
    asm("ld.const.f32 %0, [%1];" : "=f"(v) : "l"(addr));
    return v;
}

__device__ __forceinline__ float ex2f(float x) {
    float y;
    asm("ex2.approx.ftz.f32 %0, %1;" : "=f"(y) : "f"(x));
    return y;
}

__device__ __forceinline__ uint32_t smem_u32(const void* p) {
    return (uint32_t)__cvta_generic_to_shared(p);
}

__device__ __forceinline__ ull cvta_const(const void* p) {
    ull r;
    asm("cvta.to.const.u64 %0, %1;" : "=l"(r) : "l"(p));
    return r;
}

// ===========================================================================
// Kernel A: attention -> ctx written to `ctx_out` (which is d_out, as scratch)
// ===========================================================================

__global__ void __launch_bounds__(NTHREADS_A, 4)
mha_attn_kernel(const float* __restrict__ Q,
                const float* __restrict__ K,
                const float* __restrict__ V,
                const int* __restrict__ mask,   // bool promoted to int32
                float* __restrict__ ctx_out)
{
    __shared__ __align__(16) float K2s[H_][DH_][32];   // [h][i][k], key 31 zero-padded
    __shared__ __align__(16) float V2s[32][DM_];       // [k][i], row 31 zero-padded
    __shared__ __align__(16) float moff[32];           // 0 (live) or -1e30 (masked/pad)

    const int tid = threadIdx.x;
    const int b   = blockIdx.y;

    // ---------------- prologue: stage K, V, mask offsets ----------------
    {
        const float* Kb = K + (size_t)b * NK_ * DM_;
        const float* Vb = V + (size_t)b * NK_ * DM_;
        for (int idx = tid; idx < NK_ * DM_; idx += NTHREADS_A) {
            int k = idx / DM_;
            int i = idx - k * DM_;
            K2s[i >> 4][i & 15][k] = Kb[idx];
            V2s[k][i]              = Vb[idx];
        }
        for (int idx = tid; idx < DM_; idx += NTHREADS_A) {
            K2s[idx >> 4][idx & 15][31] = 0.f;
            V2s[31][idx]                = 0.f;
        }
        if (tid < 32)
            moff[tid] = (tid < NK_ && mask[b * NK_ + tid] != 0) ? 0.f : -1e30f;
    }
    __syncthreads();

    const uint32_t kbase = smem_u32(K2s);
    const uint32_t vbase = smem_u32(V2s);
    const uint32_t mbase = smem_u32(moff);

    const int row0 = blockIdx.x * ROWS_PER_BLOCK_A + tid;     // row1 = row0 + 128
    const float* qptr0 = Q + ((size_t)b * NQ_ + row0) * DM_;
    const float* qptr1 = qptr0 + (size_t)NTHREADS_A * DM_;
    float* cptr0 = ctx_out + ((size_t)b * NQ_ + row0) * DM_;
    float* cptr1 = cptr0 + (size_t)NTHREADS_A * DM_;

#pragma unroll 1
    for (int h = 0; h < H_; h++) {
        // ---- score accumulators, seeded with mask offsets (pairs along k) ----
        ull s0[16], s1[16];
#pragma unroll
        for (int kp = 0; kp < 16; kp += 2) {
            lds_v2u64(mbase + kp * 8u, s0[kp], s0[kp + 1]);
        }
#pragma unroll
        for (int kp = 0; kp < 16; kp++) s1[kp] = s0[kp];

        // ---- QK: K rows broadcast from smem, shared by both query rows ----
        const float4* q40 = (const float4*)(qptr0 + h * DH_);
        const float4* q41 = (const float4*)(qptr1 + h * DH_);
#pragma unroll
        for (int i4 = 0; i4 < 4; i4++) {
            float4 qa = q40[i4];
            float4 qb = q41[i4];
            float q0v[4] = {qa.x, qa.y, qa.z, qa.w};
            float q1v[4] = {qb.x, qb.y, qb.z, qb.w};
#pragma unroll
            for (int ii = 0; ii < 4; ii++) {
                int i = i4 * 4 + ii;
                ull qq0 = pack2(q0v[ii], q0v[ii]);
                ull qq1 = pack2(q1v[ii], q1v[ii]);
                uint32_t rowaddr = kbase + (uint32_t)((h * 16 + i) * 32 * 4);
#pragma unroll
                for (int kq = 0; kq < 8; kq++) {
                    ull ka, kb2;
                    lds_v2u64(rowaddr + kq * 16u, ka, kb2);
                    s0[2 * kq]     = fma2(qq0, ka,  s0[2 * kq]);
                    s0[2 * kq + 1] = fma2(qq0, kb2, s0[2 * kq + 1]);
                    s1[2 * kq]     = fma2(qq1, ka,  s1[2 * kq]);
                    s1[2 * kq + 1] = fma2(qq1, kb2, s1[2 * kq + 1]);
                }
            }
        }

        // ---- softmax (mask folded in as -1e30 offsets -> e = 0) ----
        float sum0 = 0.f, sum1 = 0.f;
#pragma unroll
        for (int kp = 0; kp < 16; kp++) {
            float sa, sb;
            unpack2(s0[kp], sa, sb);
            float ea = ex2f(sa * LOG2E_OVER_SCALE);
            float eb = ex2f(sb * LOG2E_OVER_SCALE);
            sum0 += ea + eb;
            s0[kp] = pack2(ea, eb);
            unpack2(s1[kp], sa, sb);
            ea = ex2f(sa * LOG2E_OVER_SCALE);
            eb = ex2f(sb * LOG2E_OVER_SCALE);
            sum1 += ea + eb;
            s1[kp] = pack2(ea, eb);
        }
        float rs0, rs1;
        asm("rcp.approx.ftz.f32 %0, %1;" : "=f"(rs0) : "f"(sum0));
        asm("rcp.approx.ftz.f32 %0, %1;" : "=f"(rs1) : "f"(sum1));
        rs0 = (sum0 > 0.f) ? rs0 : 0.f;    // all-masked -> zero ctx (B adds bias)
        rs1 = (sum1 > 0.f) ? rs1 : 0.f;
        ull rr0 = pack2(rs0, rs0);
        ull rr1 = pack2(rs1, rs1);

        // ---- AV: V rows broadcast from smem, shared by both query rows ----
        ull c0[8], c1[8];
#pragma unroll
        for (int ip = 0; ip < 8; ip++) { c0[ip] = 0ull; c1[ip] = 0ull; }

#pragma unroll
        for (int kp = 0; kp < 16; kp++) {
            float pa0, pb0, pa1, pb1;
            unpack2(s0[kp], pa0, pb0);
            unpack2(s1[kp], pa1, pb1);
            ull ppa0 = pack2(pa0, pa0), ppb0 = pack2(pb0, pb0);
            ull ppa1 = pack2(pa1, pa1), ppb1 = pack2(pb1, pb1);
            uint32_t va  = vbase + (uint32_t)(((2 * kp) * DM_ + h * DH_) * 4);
            uint32_t vb2 = va + DM_ * 4u;
#pragma unroll
            for (int iq = 0; iq < 4; iq++) {
                ull v0, v1;
                lds_v2u64(va + iq * 16u, v0, v1);
                c0[2 * iq]     = fma2(ppa0, v0, c0[2 * iq]);
                c0[2 * iq + 1] = fma2(ppa0, v1, c0[2 * iq + 1]);
                c1[2 * iq]     = fma2(ppa1, v0, c1[2 * iq]);
                c1[2 * iq + 1] = fma2(ppa1, v1, c1[2 * iq + 1]);
                lds_v2u64(vb2 + iq * 16u, v0, v1);
                c0[2 * iq]     = fma2(ppb0, v0, c0[2 * iq]);
                c0[2 * iq + 1] = fma2(ppb0, v1, c0[2 * iq + 1]);
                c1[2 * iq]     = fma2(ppb1, v0, c1[2 * iq]);
                c1[2 * iq + 1] = fma2(ppb1, v1, c1[2 * iq + 1]);
            }
        }

        // ---- normalize and write this head's ctx straight to global ----
#pragma unroll
        for (int iq = 0; iq < 4; iq++) {
            float x0, x1, x2, x3;
            ull p0 = mul2(c0[2 * iq], rr0);
            ull p1 = mul2(c0[2 * iq + 1], rr0);
            unpack2(p0, x0, x1);
            unpack2(p1, x2, x3);
            *(float4*)(cptr0 + h * DH_ + iq * 4) = make_float4(x0, x1, x2, x3);
            p0 = mul2(c1[2 * iq], rr1);
            p1 = mul2(c1[2 * iq + 1], rr1);
            unpack2(p0, x0, x1);
            unpack2(p1, x2, x3);
            *(float4*)(cptr1 + h * DH_ + iq * 4) = make_float4(x0, x1, x2, x3);
        }
    }
}

// ===========================================================================
// Kernel B: in-place projection on d_out: row <- row @ W^T + b
// ===========================================================================

__global__ void __launch_bounds__(NTHREADS_B, 2)
mha_proj_kernel(float* out)
{
    const int row = blockIdx.x * NTHREADS_B + threadIdx.x;
    float* p = out + (size_t)row * DM_;

    const ull wcb = cvta_const(cW);
    const ull bcb = cvta_const(cb);

    // Load full ctx row into registers (32 x u64 = 64 floats).
    ull ctx[32];
#pragma unroll
    for (int m = 0; m < 16; m++) {
        float4 v = ((const float4*)p)[m];
        ctx[2 * m]     = pack2(v.x, v.y);
        ctx[2 * m + 1] = pack2(v.z, v.w);
    }

    // out_j = cb[j] + sum_i ctx_i * cW[j][i]  (original W layout, uniform addrs)
#pragma unroll 1
    for (int jg = 0; jg < 16; jg++) {
        float o[4];
#pragma unroll
        for (int jj = 0; jj < 4; jj++) {
            int j = jg * 4 + jj;
            ull wa = wcb + (ull)(j * DM_ * 4);
            ull a0 = 0ull, a1 = 0ull;
#pragma unroll
            for (int t = 0; t < 16; t++) {
                ull w0, w1;
                ldc_v2u64(wa + t * 16u, w0, w1);
                a0 = fma2(ctx[2 * t],     w0, a0);
                a1 = fma2(ctx[2 * t + 1], w1, a1);
            }
            float bj = ldc_f32(bcb + (ull)(j * 4));
            float x, y, z, w;
            unpack2(a0, x, y);
            unpack2(a1, z, w);
            o[jj] = bj + ((x + y) + (z + w));
        }
        *(float4*)(p + jg * 4) = make_float4(o[0], o[1], o[2], o[3]);
    }
}

// ---------------------------------------------------------------------------

extern "C" void kernel_launch(void* const* d_in, const int* in_sizes, int n_in,
                              void* d_out, int out_size)
{
    const float* Q    = (const float*)d_in[0];
    const float* K    = (const float*)d_in[1];
    const float* V    = (const float*)d_in[2];
    const int*   mask = (const int*)d_in[3];
    const float* W    = (const float*)d_in[4];
    const float* bias = (const float*)d_in[5];
    float*       out  = (float*)d_out;

    // Graph-capturable async d2d copies into the constant bank.
    cudaMemcpyToSymbolAsync(cW, W,    DM_ * DM_ * sizeof(float), 0,
                            cudaMemcpyDeviceToDevice, 0);
    cudaMemcpyToSymbolAsync(cb, bias, DM_ * sizeof(float), 0,
                            cudaMemcpyDeviceToDevice, 0);

    dim3 gridA(NQ_ / ROWS_PER_BLOCK_A, B_);
    mha_attn_kernel<<<gridA, NTHREADS_A>>>(Q, K, V, mask, out);

    dim3 gridB((B_ * NQ_) / NTHREADS_B);
    mha_proj_kernel<<<gridB, NTHREADS_B>>>(out);
}

// round 5
// speedup vs baseline: 1.9080x; 1.9080x over previous
#include <cuda_runtime.h>
#include <cstdint>

// Problem constants
#define B_   32
#define NQ_  16384
#define NK_  31
#define DM_  64
#define H_   4
#define DH_  16

#define NTHREADS  128
#define ROWS_PER_BLOCK (NTHREADS * 2)   // 256 (2 rows per thread)

// log2(e) / sqrt(d_head)
#define LOG2E_OVER_SCALE 0.36067376022224085f

typedef unsigned long long ull;

// ---------------- f32x2 helpers (SASS FFMA2 path, PTX-only) ----------------

__device__ __forceinline__ ull pack2(float lo, float hi) {
    ull r;
    asm("mov.b64 %0, {%1, %2};" : "=l"(r) : "f"(lo), "f"(hi));
    return r;
}

__device__ __forceinline__ void unpack2(ull v, float& lo, float& hi) {
    asm("mov.b64 {%0, %1}, %2;" : "=f"(lo), "=f"(hi) : "l"(v));
}

__device__ __forceinline__ ull fma2(ull a, ull b, ull c) {
    ull d;
    asm("fma.rn.f32x2 %0, %1, %2, %3;" : "=l"(d) : "l"(a), "l"(b), "l"(c));
    return d;
}

__device__ __forceinline__ ull add2(ull a, ull b) {
    ull d;
    asm("add.rn.f32x2 %0, %1, %2;" : "=l"(d) : "l"(a), "l"(b));
    return d;
}

__device__ __forceinline__ ull mul2(ull a, ull b) {
    ull d;
    asm("mul.rn.f32x2 %0, %1, %2;" : "=l"(d) : "l"(a), "l"(b));
    return d;
}

__device__ __forceinline__ void lds_v2u64(uint32_t addr, ull& a, ull& b) {
    asm("ld.shared.v2.u64 {%0, %1}, [%2];" : "=l"(a), "=l"(b) : "r"(addr));
}

__device__ __forceinline__ float lds_f32(uint32_t addr) {
    float v;
    asm("ld.shared.f32 %0, [%1];" : "=f"(v) : "r"(addr));
    return v;
}

__device__ __forceinline__ float ex2f(float x) {
    float y;
    asm("ex2.approx.ftz.f32 %0, %1;" : "=f"(y) : "f"(x));
    return y;
}

__device__ __forceinline__ uint32_t smem_u32(const void* p) {
    return (uint32_t)__cvta_generic_to_shared(p);
}

// ---------------------------------------------------------------------------

__global__ void __launch_bounds__(NTHREADS, 2)
mha_fused_kernel(const float* __restrict__ Q,
                 const float* __restrict__ K,
                 const float* __restrict__ V,
                 const int* __restrict__ mask,    // bool promoted to int32
                 const float* __restrict__ Wout,  // [j][i] row-major, out = x @ W^T
                 const float* __restrict__ bout,  // [64]
                 float* __restrict__ out)
{
    __shared__ __align__(16) float K2s[H_][DH_][32];   // [h][i][k], key 31 zero-padded
    __shared__ __align__(16) float V2s[32][DM_];       // [k][i], row 31 zero-padded
    __shared__ __align__(16) float W2s[DM_][DM_];      // ORIGINAL layout: W2s[j][i]
    __shared__ __align__(16) float moff[32];           // 0 (live) or -1e30 (masked/pad)
    __shared__ __align__(16) float b2s[DM_];

    const int tid = threadIdx.x;
    const int b   = blockIdx.y;

    // ---------------- prologue: stage K, V, W, mask, bias ----------------
    {
        const float* Kb = K + (size_t)b * NK_ * DM_;
        const float* Vb = V + (size_t)b * NK_ * DM_;
        for (int idx = tid; idx < NK_ * DM_; idx += NTHREADS) {
            int k = idx / DM_;
            int i = idx - k * DM_;
            K2s[i >> 4][i & 15][k] = Kb[idx];
            V2s[k][i]              = Vb[idx];
        }
        for (int idx = tid; idx < DM_; idx += NTHREADS) {
            K2s[idx >> 4][idx & 15][31] = 0.f;
            V2s[31][idx]                = 0.f;
        }
        // W stays in original [j][i] layout: fully coalesced 16B copies.
        for (int idx = tid; idx < (DM_ * DM_) / 4; idx += NTHREADS) {
            ((float4*)W2s)[idx] = ((const float4*)Wout)[idx];
        }
        if (tid < 32)
            moff[tid] = (tid < NK_ && mask[b * NK_ + tid] != 0) ? 0.f : -1e30f;
        if (tid < DM_) b2s[tid] = bout[tid];
    }
    __syncthreads();

    const uint32_t kbase = smem_u32(K2s);
    const uint32_t vbase = smem_u32(V2s);
    const uint32_t wbase = smem_u32(W2s);
    const uint32_t mbase = smem_u32(moff);
    const uint32_t bbase = smem_u32(b2s);

    const int row0 = blockIdx.x * ROWS_PER_BLOCK + tid;     // row1 = row0 + 128
    const float* qptr0 = Q + ((size_t)b * NQ_ + row0) * DM_;
    const float* qptr1 = qptr0 + (size_t)NTHREADS * DM_;

    // Per-row context (4 heads x 16 floats) as f32x2 pairs: 32 u64 per row.
    ull ctx0[32], ctx1[32];

#pragma unroll 1
    for (int h = 0; h < H_; h++) {
        // ---- score accumulators, seeded with mask offsets (pairs along k) ----
        ull s0[16], s1[16];
#pragma unroll
        for (int kp = 0; kp < 16; kp += 2) {
            lds_v2u64(mbase + kp * 8u, s0[kp], s0[kp + 1]);
        }
#pragma unroll
        for (int kp = 0; kp < 16; kp++) s1[kp] = s0[kp];

        // ---- QK: K rows broadcast from smem, shared by both query rows ----
        const float4* q40 = (const float4*)(qptr0 + h * DH_);
        const float4* q41 = (const float4*)(qptr1 + h * DH_);
#pragma unroll
        for (int i4 = 0; i4 < 4; i4++) {
            float4 qa = q40[i4];
            float4 qb = q41[i4];
            float q0v[4] = {qa.x, qa.y, qa.z, qa.w};
            float q1v[4] = {qb.x, qb.y, qb.z, qb.w};
#pragma unroll
            for (int ii = 0; ii < 4; ii++) {
                int i = i4 * 4 + ii;
                ull qq0 = pack2(q0v[ii], q0v[ii]);
                ull qq1 = pack2(q1v[ii], q1v[ii]);
                uint32_t rowaddr = kbase + (uint32_t)((h * 16 + i) * 32 * 4);
#pragma unroll
                for (int kq = 0; kq < 8; kq++) {
                    ull ka, kb2;
                    lds_v2u64(rowaddr + kq * 16u, ka, kb2);
                    s0[2 * kq]     = fma2(qq0, ka,  s0[2 * kq]);
                    s0[2 * kq + 1] = fma2(qq0, kb2, s0[2 * kq + 1]);
                    s1[2 * kq]     = fma2(qq1, ka,  s1[2 * kq]);
                    s1[2 * kq + 1] = fma2(qq1, kb2, s1[2 * kq + 1]);
                }
            }
        }

        // ---- softmax (mask folded in as -1e30 offsets -> e = 0) ----
        float sum0 = 0.f, sum1 = 0.f;
#pragma unroll
        for (int kp = 0; kp < 16; kp++) {
            float sa, sb;
            unpack2(s0[kp], sa, sb);
            float ea = ex2f(sa * LOG2E_OVER_SCALE);
            float eb = ex2f(sb * LOG2E_OVER_SCALE);
            sum0 += ea + eb;
            s0[kp] = pack2(ea, eb);
            unpack2(s1[kp], sa, sb);
            ea = ex2f(sa * LOG2E_OVER_SCALE);
            eb = ex2f(sb * LOG2E_OVER_SCALE);
            sum1 += ea + eb;
            s1[kp] = pack2(ea, eb);
        }
        float rs0, rs1;
        asm("rcp.approx.ftz.f32 %0, %1;" : "=f"(rs0) : "f"(sum0));
        asm("rcp.approx.ftz.f32 %0, %1;" : "=f"(rs1) : "f"(sum1));
        rs0 = (sum0 > 0.f) ? rs0 : 0.f;    // all-masked -> zero ctx (bias-only out)
        rs1 = (sum1 > 0.f) ? rs1 : 0.f;
        ull rr0 = pack2(rs0, rs0);
        ull rr1 = pack2(rs1, rs1);

        // ---- AV: V rows broadcast from smem, shared by both query rows ----
        ull c0[8], c1[8];
#pragma unroll
        for (int ip = 0; ip < 8; ip++) { c0[ip] = 0ull; c1[ip] = 0ull; }

#pragma unroll
        for (int kp = 0; kp < 16; kp++) {
            float pa0, pb0, pa1, pb1;
            unpack2(s0[kp], pa0, pb0);
            unpack2(s1[kp], pa1, pb1);
            ull ppa0 = pack2(pa0, pa0), ppb0 = pack2(pb0, pb0);
            ull ppa1 = pack2(pa1, pa1), ppb1 = pack2(pb1, pb1);
            uint32_t va  = vbase + (uint32_t)(((2 * kp) * DM_ + h * DH_) * 4);
            uint32_t vb2 = va + DM_ * 4u;
#pragma unroll
            for (int iq = 0; iq < 4; iq++) {
                ull v0, v1;
                lds_v2u64(va + iq * 16u, v0, v1);
                c0[2 * iq]     = fma2(ppa0, v0, c0[2 * iq]);
                c0[2 * iq + 1] = fma2(ppa0, v1, c0[2 * iq + 1]);
                c1[2 * iq]     = fma2(ppa1, v0, c1[2 * iq]);
                c1[2 * iq + 1] = fma2(ppa1, v1, c1[2 * iq + 1]);
                lds_v2u64(vb2 + iq * 16u, v0, v1);
                c0[2 * iq]     = fma2(ppb0, v0, c0[2 * iq]);
                c0[2 * iq + 1] = fma2(ppb0, v1, c0[2 * iq + 1]);
                c1[2 * iq]     = fma2(ppb1, v0, c1[2 * iq]);
                c1[2 * iq + 1] = fma2(ppb1, v1, c1[2 * iq + 1]);
            }
        }

        // ---- normalize into persistent ctx slots ----
#pragma unroll
        for (int ip = 0; ip < 8; ip++) {
            ctx0[h * 8 + ip] = mul2(c0[ip], rr0);
            ctx1[h * 8 + ip] = mul2(c1[ip], rr1);
        }
    }

    // ---------------- projection: W rows broadcast from smem ----------------
    // out[r][j] = b[j] + sum_i ctx[r][i] * W2s[j][i]
    float* optr0 = out + ((size_t)b * NQ_ + row0) * DM_;
    float* optr1 = optr0 + (size_t)NTHREADS * DM_;

#pragma unroll 1
    for (int jg = 0; jg < 16; jg++) {
        float o0[4], o1[4];
#pragma unroll
        for (int jj = 0; jj < 4; jj++) {
            int j = jg * 4 + jj;
            uint32_t wa = wbase + (uint32_t)(j * DM_ * 4);
            ull a00 = 0ull, a01 = 0ull, a10 = 0ull, a11 = 0ull;
#pragma unroll
            for (int t = 0; t < 16; t++) {
                ull w0, w1;
                lds_v2u64(wa + t * 16u, w0, w1);
                a00 = fma2(ctx0[2 * t],     w0, a00);
                a01 = fma2(ctx0[2 * t + 1], w1, a01);
                a10 = fma2(ctx1[2 * t],     w0, a10);
                a11 = fma2(ctx1[2 * t + 1], w1, a11);
            }
            float bj = lds_f32(bbase + (uint32_t)(j * 4));
            ull ar0 = add2(a00, a01);
            ull ar1 = add2(a10, a11);
            float x, y;
            unpack2(ar0, x, y);
            o0[jj] = bj + (x + y);
            unpack2(ar1, x, y);
            o1[jj] = bj + (x + y);
        }
        *(float4*)(optr0 + jg * 4) = make_float4(o0[0], o0[1], o0[2], o0[3]);
        *(float4*)(optr1 + jg * 4) = make_float4(o1[0], o1[1], o1[2], o1[3]);
    }
}

// ---------------------------------------------------------------------------

extern "C" void kernel_launch(void* const* d_in, const int* in_sizes, int n_in,
                              void* d_out, int out_size)
{
    const float* Q    = (const float*)d_in[0];
    const float* K    = (const float*)d_in[1];
    const float* V    = (const float*)d_in[2];
    const int*   mask = (const int*)d_in[3];
    const float* W    = (const float*)d_in[4];
    const float* bias = (const float*)d_in[5];
    float*       out  = (float*)d_out;

    dim3 grid(NQ_ / ROWS_PER_BLOCK, B_);
    mha_fused_kernel<<<grid, NTHREADS>>>(Q, K, V, mask, W, bias, out);
}